// round 15
// baseline (speedup 1.0000x reference)
#include <cuda_runtime.h>
#include <cuda_bf16.h>
#include <cuda_fp16.h>
#include <math.h>

#define NN  4096
#define EMB 256
#define NH  4
#define HC  64

typedef unsigned long long ull;

// ---- device scratch (no allocations allowed) ----
__device__ float    g_h[NN*EMB];
__device__ float    g_y[NN*EMB];
__device__ float    g_r[NH*NN];                 // e^{0.8 s_i}
__device__ float    g_ab[NH*NN*2];              // interleaved (e^{t_j}, e^{0.2 t_j})
__device__ unsigned g_adjbits[NN*(NN/32)];      // adjacency bitmask, diag=1
__device__ __half   g_hT[(size_t)NH*HC*NN];     // h transposed, fp16 (rn)
__device__ __nv_bfloat16 g_xhi[NN*EMB],  g_xlo[NN*EMB];    // x split (row-major)
__device__ __nv_bfloat16 g_atthi[NN*EMB], g_attlo[NN*EMB]; // att split (row-major)
__device__ __nv_bfloat16 g_wlhi[EMB*EMB], g_wllo[EMB*EMB]; // W_lin^T split [n][k]
__device__ __nv_bfloat16 g_wohi[EMB*EMB], g_wolo[EMB*EMB]; // W_out^T split [n][k]

__device__ __forceinline__ unsigned swz(unsigned o) { return o ^ ((o >> 3) & 0x70); }

__device__ __forceinline__ void ldsm4(unsigned& r0, unsigned& r1, unsigned& r2, unsigned& r3,
                                      unsigned a) {
    asm volatile("ldmatrix.sync.aligned.m8n8.x4.shared.b16 {%0,%1,%2,%3}, [%4];"
        : "=r"(r0), "=r"(r1), "=r"(r2), "=r"(r3) : "r"(a));
}
__device__ __forceinline__ void mma_bf(float* d, unsigned a0, unsigned a1, unsigned a2,
                                       unsigned a3, unsigned b0, unsigned b1) {
    asm volatile("mma.sync.aligned.m16n8k16.row.col.f32.bf16.bf16.f32 "
        "{%0,%1,%2,%3}, {%4,%5,%6,%7}, {%8,%9}, {%0,%1,%2,%3};"
        : "+f"(d[0]), "+f"(d[1]), "+f"(d[2]), "+f"(d[3])
        : "r"(a0), "r"(a1), "r"(a2), "r"(a3), "r"(b0), "r"(b1));
}
__device__ __forceinline__ void mma_h(float* d, unsigned a0, unsigned a1, unsigned a2,
                                      unsigned a3, unsigned b0, unsigned b1) {
    asm volatile("mma.sync.aligned.m16n8k16.row.col.f32.f16.f16.f32 "
        "{%0,%1,%2,%3}, {%4,%5,%6,%7}, {%8,%9}, {%0,%1,%2,%3};"
        : "+f"(d[0]), "+f"(d[1]), "+f"(d[2]), "+f"(d[3])
        : "r"(a0), "r"(a1), "r"(a2), "r"(a3), "r"(b0), "r"(b1));
}
__device__ __forceinline__ void cpa16(unsigned dst, const void* src) {
    asm volatile("cp.async.cg.shared.global [%0], [%1], 16;" :: "r"(dst), "l"(src));
}
__device__ __forceinline__ unsigned bfpairhi(float f0, float f1) {
    return __byte_perm(__float_as_uint(f0), __float_as_uint(f1), 0x7632);
}
__device__ __forceinline__ unsigned bfpairlo(float f0, float f1) {
    float r0 = f0 - __uint_as_float(__float_as_uint(f0) & 0xffff0000u);
    float r1 = f1 - __uint_as_float(__float_as_uint(f1) & 0xffff0000u);
    unsigned r; asm("cvt.rn.bf16x2.f32 %0, %1, %2;" : "=r"(r) : "f"(r1), "f"(r0));
    return r;
}

// ---------------------------------------------------------------------------
// Fused splits: blocks [0,2048) x->bf16 hi/lo; [2048,2176) W_lin; [2176,2304) W_out.
// ---------------------------------------------------------------------------
__global__ __launch_bounds__(256) void split_all_kernel(
    const float* __restrict__ x, const float* __restrict__ W_lin,
    const float* __restrict__ W_out)
{
    int b = blockIdx.x;
    if (b < 2048) {
        int i = b * 256 + threadIdx.x;
        float2 v = ((const float2*)x)[i];
        ((unsigned*)g_xhi)[i] = bfpairhi(v.x, v.y);
        ((unsigned*)g_xlo)[i] = bfpairlo(v.x, v.y);
    } else {
        const float* W = (b < 2176) ? W_lin : W_out;
        __nv_bfloat16* whi = (b < 2176) ? g_wlhi : g_wohi;
        __nv_bfloat16* wlo = (b < 2176) ? g_wllo : g_wolo;
        int idx = ((b - 2048) & 127) * 256 + threadIdx.x;
        int n = idx >> 7, kp = (idx & 127) * 2;
        float f0 = W[kp * EMB + n], f1 = W[(kp + 1) * EMB + n];
        ((unsigned*)whi)[n * 128 + (kp >> 1)] = bfpairhi(f0, f1);
        ((unsigned*)wlo)[n * 128 + (kp >> 1)] = bfpairlo(f0, f1);
    }
}

// ---------------------------------------------------------------------------
// Dense GEMM (R12 version): bf16 3-product, 2-stage cp.async, 256 threads,
// warp w: rows (w>>1)*32..+32, cols (w&1)*32..+32.
// ---------------------------------------------------------------------------
#define GM_A 0        // 2 bufs x (hi 16K + lo 16K)
#define GM_B 65536    // 2 bufs x (hi 8K + lo 8K)
#define GM_TOT 98304

__global__ __launch_bounds__(256) void gemm_mma_kernel(
    const __nv_bfloat16* __restrict__ Ahi, const __nv_bfloat16* __restrict__ Alo,
    const __nv_bfloat16* __restrict__ Bhi, const __nv_bfloat16* __restrict__ Blo,
    const float* __restrict__ bias, float* __restrict__ Co)
{
    extern __shared__ char smc[];
    const unsigned sb = (unsigned)__cvta_generic_to_shared(smc);
    const int tid  = threadIdx.x;
    const int m0   = blockIdx.y * 128;
    const int n0   = blockIdx.x * 64;
    const int lane = tid & 31;
    const int warp = tid >> 5;
    const int mrow  = (warp >> 1) * 32;
    const int nside = warp & 1;
    const int grp  = lane >> 3, lr = lane & 7;
    const unsigned afrag = (unsigned)(lr + ((grp & 1) << 3));
    const unsigned khalf = (unsigned)((grp >> 1) << 4);

    float acc[2][4][4];
#pragma unroll
    for (int m = 0; m < 2; m++)
#pragma unroll
        for (int n = 0; n < 4; n++)
#pragma unroll
            for (int e = 0; e < 4; e++) acc[m][n][e] = 0.f;

    auto load_chunk = [&](int kc, int buf) {
        const unsigned ab = GM_A + buf * 32768;
        const unsigned bb = GM_B + buf * 16384;
        const int k0 = kc * 64;
#pragma unroll
        for (int r = 0; r < 4; r++) {
            int ch = tid + r * 256;
            int row = ch >> 3, q = ch & 7;
            unsigned so = swz((unsigned)(row * 128 + q * 16));
            size_t off = (size_t)(m0 + row) * EMB + k0 + q * 8;
            cpa16(sb + ab + so,         Ahi + off);
            cpa16(sb + ab + 16384 + so, Alo + off);
        }
#pragma unroll
        for (int r = 0; r < 2; r++) {
            int ch = tid + r * 256;
            int n = ch >> 3, q = ch & 7;
            unsigned so = swz((unsigned)(n * 128 + q * 16));
            size_t off = (size_t)(n0 + n) * EMB + k0 + q * 8;
            cpa16(sb + bb + so,        Bhi + off);
            cpa16(sb + bb + 8192 + so, Blo + off);
        }
        asm volatile("cp.async.commit_group;" ::: "memory");
    };

    load_chunk(0, 0);
    for (int kc = 0; kc < 4; kc++) {
        const int buf = kc & 1;
        __syncthreads();
        if (kc < 3) load_chunk(kc + 1, buf ^ 1);
        if (kc < 3) { asm volatile("cp.async.wait_group 1;" ::: "memory"); }
        else        { asm volatile("cp.async.wait_group 0;" ::: "memory"); }
        __syncthreads();

        const unsigned ab = GM_A + buf * 32768;
        const unsigned bb = GM_B + buf * 16384;
#pragma unroll
        for (int kk = 0; kk < 4; kk++) {
            unsigned ah[2][4], al[2][4];
#pragma unroll
            for (int m = 0; m < 2; m++) {
                unsigned aoff = swz((unsigned)(mrow + m * 16 + afrag) * 128
                                    + (unsigned)(kk * 32) + khalf);
                ldsm4(ah[m][0], ah[m][1], ah[m][2], ah[m][3], sb + ab + aoff);
                ldsm4(al[m][0], al[m][1], al[m][2], al[m][3], sb + ab + 16384 + aoff);
            }
#pragma unroll
            for (int l = 0; l < 2; l++) {
                unsigned nrow = (unsigned)(nside * 32 + l * 16 + afrag);
                unsigned boff = swz(nrow * 128 + (unsigned)(kk * 32) + khalf);
                unsigned bh0, bh1, bh2, bh3, bl0, bl1, bl2, bl3;
                ldsm4(bh0, bh1, bh2, bh3, sb + bb + boff);
                ldsm4(bl0, bl1, bl2, bl3, sb + bb + 8192 + boff);
#pragma unroll
                for (int m = 0; m < 2; m++) {
                    mma_bf(acc[m][2*l],   ah[m][0], ah[m][1], ah[m][2], ah[m][3], bh0, bh2);
                    mma_bf(acc[m][2*l],   ah[m][0], ah[m][1], ah[m][2], ah[m][3], bl0, bl2);
                    mma_bf(acc[m][2*l],   al[m][0], al[m][1], al[m][2], al[m][3], bh0, bh2);
                    mma_bf(acc[m][2*l+1], ah[m][0], ah[m][1], ah[m][2], ah[m][3], bh1, bh3);
                    mma_bf(acc[m][2*l+1], ah[m][0], ah[m][1], ah[m][2], ah[m][3], bl1, bl3);
                    mma_bf(acc[m][2*l+1], al[m][0], al[m][1], al[m][2], al[m][3], bh1, bh3);
                }
            }
        }
    }

    int cb = (lane & 3) * 2;
#pragma unroll
    for (int m = 0; m < 2; m++) {
        int r0 = m0 + mrow + m * 16 + (lane >> 2);
        int r1 = r0 + 8;
#pragma unroll
        for (int j = 0; j < 4; j++) {
            int col = n0 + nside * 32 + j * 8 + cb;
            float b0 = bias ? __ldg(bias + col)     : 0.f;
            float b1 = bias ? __ldg(bias + col + 1) : 0.f;
            *(float2*)&Co[(size_t)r0 * EMB + col] =
                make_float2(acc[m][j][0] + b0, acc[m][j][1] + b1);
            *(float2*)&Co[(size_t)r1 * EMB + col] =
                make_float2(acc[m][j][2] + b0, acc[m][j][3] + b1);
        }
    }
}

// ---------------------------------------------------------------------------
// adj -> bitmask (forced self-loop)
// ---------------------------------------------------------------------------
__global__ __launch_bounds__(256) void adjbits_kernel(const int* __restrict__ adj)
{
    int row  = blockIdx.x;
    int lane = threadIdx.x & 31;
    int w    = threadIdx.x >> 5;
#pragma unroll
    for (int wd = w; wd < NN/32; wd += 8) {
        int v = adj[(long)row * NN + wd * 32 + lane];
        unsigned bits = __ballot_sync(0xffffffffu, v != 0);
        if ((row >> 5) == wd) bits |= 1u << (row & 31);
        if (lane == 0) g_adjbits[row * (NN/32) + wd] = bits;
    }
}

// ---------------------------------------------------------------------------
// Fused ht + prep: block (jtile, head). Loads h tile once; emits transposed
// fp16 hT AND the per-node attention scalars r/ab for these 64 nodes.
// ---------------------------------------------------------------------------
__global__ __launch_bounds__(256) void ht_prep_kernel(
    const float* __restrict__ att_src, const float* __restrict__ att_dst)
{
    __shared__ float s[64][65];
    const int hd = blockIdx.y, jt = blockIdx.x * 64;
    const int t = threadIdx.x;
    {
        int r = t >> 2, cq = t & 3;
        const float4* src = (const float4*)(g_h + (size_t)(jt + r) * EMB + hd * HC + cq * 16);
#pragma unroll
        for (int u = 0; u < 4; u++) {
            float4 v = src[u];
            int cb = cq * 16 + u * 4;
            s[r][cb] = v.x; s[r][cb+1] = v.y; s[r][cb+2] = v.z; s[r][cb+3] = v.w;
        }
    }
    __syncthreads();

    // transpose -> fp16 hT
    {
        int c = t >> 2, jq = t & 3;
        unsigned hi[8];
#pragma unroll
        for (int e = 0; e < 8; e++) {
            __half2 hp = __floats2half2_rn(s[jq*16 + 2*e][c], s[jq*16 + 2*e + 1][c]);
            hi[e] = *(unsigned*)&hp;
        }
        size_t o = (size_t)(hd * HC + c) * NN + jt + jq * 16;
        *(uint4*)(g_hT + o)       = make_uint4(hi[0], hi[1], hi[2], hi[3]);
        *((uint4*)(g_hT + o) + 1) = make_uint4(hi[4], hi[5], hi[6], hi[7]);
    }

    // prep: 4 threads per node, 16 cols each
    {
        int node = t >> 2, q = t & 3;
        float sdot = 0.f, tdot = 0.f;
#pragma unroll
        for (int k = 0; k < 16; k++) {
            float hv = s[node][q * 16 + k];
            sdot += hv * __ldg(att_dst + hd * HC + q * 16 + k);
            tdot += hv * __ldg(att_src + hd * HC + q * 16 + k);
        }
        sdot += __shfl_xor_sync(0xffffffffu, sdot, 1);
        tdot += __shfl_xor_sync(0xffffffffu, tdot, 1);
        sdot += __shfl_xor_sync(0xffffffffu, sdot, 2);
        tdot += __shfl_xor_sync(0xffffffffu, tdot, 2);
        if (q == 0) {
            int idx = hd * NN + jt + node;
            g_r[idx]        = expf(0.8f * sdot);
            g_ab[2*idx]     = expf(tdot);
            g_ab[2*idx + 1] = expf(0.2f * tdot);
        }
    }
}

// ---------------------------------------------------------------------------
// GAT aggregation, fp16 single-product mma. 64-ROW tiles -> grid (64,4)=256
// blocks, ~2 blocks/SM (cross-block latency hiding). 256 threads, 8 warps;
// warp w: rows (w>>1)*16..+16, cols (w&1)*32..+32. Phase C: 4 thr/row, 16 j.
// Weights pre-scaled 1/16. Double-buffered, 1 barrier/tile.
// ---------------------------------------------------------------------------
#define SM_AB   0         // 32768 B
#define SM_A    32768     // 2 bufs x 8192 (fp16 c, 64 rows)
#define SM_B    49152     // 2 bufs x 8192 (fp16 hT)
#define SM_D    65536     // 1024 B (256 floats)
#define SM_TOT  66560

__global__ __launch_bounds__(256, 2) void gat_mma_kernel(const float* __restrict__ bias_att)
{
    extern __shared__ char smc[];
    const unsigned sb = (unsigned)__cvta_generic_to_shared(smc);
    const int tid  = threadIdx.x;
    const int hd   = blockIdx.y;
    const int i0   = blockIdx.x * 64;
    const int lane = tid & 31;
    const int warp = tid >> 5;
    const int mrow  = (warp >> 1) * 16;   // 0,16,32,48
    const int nside = warp & 1;

    {
        const float4* src = (const float4*)(g_ab + (size_t)hd * NN * 2);
        float4* dst = (float4*)(smc + SM_AB);
        for (int k = tid; k < NN / 2; k += 256) dst[k] = src[k];
    }

    // phase-C: 4 threads per row, 16 j each
    const int row = tid >> 2;
    const int q4  = tid & 3;
    const float ri = g_r[hd * NN + i0 + row] * 0.0625f;
    const unsigned* abw = g_adjbits + (size_t)(i0 + row) * (NN / 32);
    const float4* abt4  = (const float4*)(smc + SM_AB);
    float dreg = 0.f;

    const int grp = lane >> 3, lr = lane & 7;
    const unsigned khalf = (unsigned)((grp >> 1) << 4);
    const unsigned afrag = (unsigned)(lr + ((grp & 1) << 3));

    const __half* bsrc0 = g_hT + (size_t)hd * HC * NN;

    float acc[4][4];
#pragma unroll
    for (int n = 0; n < 4; n++)
#pragma unroll
        for (int e = 0; e < 4; e++) acc[n][e] = 0.f;

    __syncthreads();   // ab ready

    for (int t = 0; t < 64; t++) {
        const int j0  = t * 64;
        const int buf = t & 1;
        const unsigned abase = SM_A + buf * 8192;
        const unsigned bbase = SM_B + buf * 8192;

        // B tile via cp.async: hT [64 c][64 j] fp16, SW128
#pragma unroll
        for (int r = 0; r < 2; r++) {
            int ch = tid + r * 256;
            int cc = ch >> 3, q = ch & 7;
            unsigned so = swz((unsigned)(cc * 128 + q * 16));
            cpa16(sb + bbase + so, bsrc0 + (size_t)cc * NN + j0 + q * 8);
        }
        asm volatile("cp.async.commit_group;" ::: "memory");

        // A tile: 16 j per thread (j = q4*16 ..)
        {
            unsigned wb = abw[(j0 >> 5) + (q4 >> 1)];
            const int shbase = (q4 & 1) * 16;
            const float4* abt = abt4 + (j0 >> 1) + q4 * 8;
#pragma unroll
            for (int q = 0; q < 2; q++) {
                unsigned hp4[4];
#pragma unroll
                for (int p = 0; p < 4; p++) {
                    float4 v = abt[q * 4 + p];
                    int sh = shbase + q * 8 + p * 2;
                    float c0 = ((wb >> sh) & 1u)       ? fmaxf(ri * v.x, 0.0625f * v.y) : 0.f;
                    float c1 = ((wb >> (sh + 1)) & 1u) ? fmaxf(ri * v.z, 0.0625f * v.w) : 0.f;
                    dreg += c0 + c1;
                    __half2 hh = __floats2half2_rn(c0, c1);
                    hp4[p] = *(unsigned*)&hh;
                }
                unsigned so = swz((unsigned)(row * 128 + q4 * 32 + q * 16));
                *(uint4*)(smc + abase + so) = make_uint4(hp4[0], hp4[1], hp4[2], hp4[3]);
            }
        }
        asm volatile("cp.async.wait_group 0;" ::: "memory");
        __syncthreads();

        // MMA: warp covers rows [mrow,mrow+16), cols [nside*32,+32)
#pragma unroll
        for (int kk = 0; kk < 4; kk++) {
            unsigned a0, a1, a2, a3;
            unsigned aoff = swz((unsigned)(mrow + afrag) * 128
                                + (unsigned)(kk * 32) + khalf);
            ldsm4(a0, a1, a2, a3, sb + abase + aoff);
#pragma unroll
            for (int l = 0; l < 2; l++) {
                unsigned nrow = (unsigned)(nside * 32 + l * 16 + afrag);
                unsigned boff = swz(nrow * 128 + (unsigned)(kk * 32) + khalf);
                unsigned b0, b1, b2, b3;
                ldsm4(b0, b1, b2, b3, sb + bbase + boff);
                mma_h(acc[2*l],   a0, a1, a2, a3, b0, b2);
                mma_h(acc[2*l+1], a0, a1, a2, a3, b1, b3);
            }
        }
    }

    ((float*)(smc + SM_D))[tid] = dreg;
    __syncthreads();

    // epilogue: normalize, +bias, split to bf16 hi/lo for gemm2
    {
        const float* dsm = (const float*)(smc + SM_D);
        int r0 = mrow + (lane >> 2);
        int r1 = r0 + 8;
        float inv0 = 1.0f / (dsm[4*r0] + dsm[4*r0+1] + dsm[4*r0+2] + dsm[4*r0+3]);
        float inv1 = 1.0f / (dsm[4*r1] + dsm[4*r1+1] + dsm[4*r1+2] + dsm[4*r1+3]);
        int cb = (lane & 3) * 2;
#pragma unroll
        for (int j = 0; j < 4; j++) {
            int col = nside * 32 + j * 8 + cb;
            float b0 = __ldg(bias_att + hd * HC + col);
            float b1 = __ldg(bias_att + hd * HC + col + 1);
            float v00 = acc[j][0] * inv0 + b0, v01 = acc[j][1] * inv0 + b1;
            float v10 = acc[j][2] * inv1 + b0, v11 = acc[j][3] * inv1 + b1;
            size_t o0 = ((size_t)(i0 + r0) * EMB + hd * HC + col) >> 1;
            size_t o1 = ((size_t)(i0 + r1) * EMB + hd * HC + col) >> 1;
            ((unsigned*)g_atthi)[o0] = bfpairhi(v00, v01);
            ((unsigned*)g_attlo)[o0] = bfpairlo(v00, v01);
            ((unsigned*)g_atthi)[o1] = bfpairhi(v10, v11);
            ((unsigned*)g_attlo)[o1] = bfpairlo(v10, v11);
        }
    }
}

// ---------------------------------------------------------------------------
// LayerNorm over last dim (256), one block per row.
// ---------------------------------------------------------------------------
__global__ __launch_bounds__(256) void ln_kernel(
    const float* __restrict__ gamma, const float* __restrict__ beta,
    float* __restrict__ out)
{
    __shared__ float red1[8], red2[8];
    int row = blockIdx.x;
    int tid = threadIdx.x;
    float v = g_y[row * EMB + tid];

    float s = v;
#pragma unroll
    for (int o = 16; o; o >>= 1) s += __shfl_xor_sync(0xffffffffu, s, o);
    if ((tid & 31) == 0) red1[tid >> 5] = s;
    __syncthreads();
    float mu = 0.f;
#pragma unroll
    for (int k = 0; k < 8; k++) mu += red1[k];
    mu *= (1.0f / EMB);

    float d = v - mu;
    float q = d * d;
#pragma unroll
    for (int o = 16; o; o >>= 1) q += __shfl_xor_sync(0xffffffffu, q, o);
    if ((tid & 31) == 0) red2[tid >> 5] = q;
    __syncthreads();
    float var = 0.f;
#pragma unroll
    for (int k = 0; k < 8; k++) var += red2[k];
    var *= (1.0f / EMB);

    out[row * EMB + tid] = d * rsqrtf(var + 1e-5f) * gamma[tid] + beta[tid];
}

// ---------------------------------------------------------------------------
extern "C" void kernel_launch(void* const* d_in, const int* in_sizes, int n_in,
                              void* d_out, int out_size)
{
    const float* x        = (const float*)d_in[0];
    const int*   adj      = (const int*)  d_in[1];
    const float* W_lin    = (const float*)d_in[2];
    const float* att_src  = (const float*)d_in[3];
    const float* att_dst  = (const float*)d_in[4];
    const float* bias_att = (const float*)d_in[5];
    const float* W_out    = (const float*)d_in[6];
    const float* b_out    = (const float*)d_in[7];
    const float* gamma    = (const float*)d_in[8];
    const float* beta     = (const float*)d_in[9];
    float* out = (float*)d_out;

    float *p_h, *p_y;
    cudaGetSymbolAddress((void**)&p_h, g_h);
    cudaGetSymbolAddress((void**)&p_y, g_y);
    __nv_bfloat16 *p_xhi, *p_xlo, *p_athi, *p_atlo, *p_wlhi, *p_wllo, *p_wohi, *p_wolo;
    cudaGetSymbolAddress((void**)&p_xhi,  g_xhi);
    cudaGetSymbolAddress((void**)&p_xlo,  g_xlo);
    cudaGetSymbolAddress((void**)&p_athi, g_atthi);
    cudaGetSymbolAddress((void**)&p_atlo, g_attlo);
    cudaGetSymbolAddress((void**)&p_wlhi, g_wlhi);
    cudaGetSymbolAddress((void**)&p_wllo, g_wllo);
    cudaGetSymbolAddress((void**)&p_wohi, g_wohi);
    cudaGetSymbolAddress((void**)&p_wolo, g_wolo);

    cudaFuncSetAttribute(gat_mma_kernel,  cudaFuncAttributeMaxDynamicSharedMemorySize, SM_TOT);
    cudaFuncSetAttribute(gemm_mma_kernel, cudaFuncAttributeMaxDynamicSharedMemorySize, GM_TOT);

    dim3 gemm_grid(EMB / 64, NN / 128);  // (4, 32) = 128 blocks

    // splits (fused)
    split_all_kernel<<<2304, 256>>>(x, W_lin, W_out);
    // 1) h = x @ W_lin
    gemm_mma_kernel<<<gemm_grid, 256, GM_TOT>>>(p_xhi, p_xlo, p_wlhi, p_wllo, nullptr, p_h);
    adjbits_kernel<<<NN, 256>>>(adj);
    // 2) fused transpose + attention scalars
    ht_prep_kernel<<<dim3(NN / 64, NH), 256>>>(att_src, att_dst);
    // 3) fp16 single-product masked-softmax aggregation, 64-row tiles
    gat_mma_kernel<<<dim3(NN / 64, NH), 256, SM_TOT>>>(bias_att);
    // 4) y = att @ W_out + b_out
    gemm_mma_kernel<<<gemm_grid, 256, GM_TOT>>>(p_athi, p_atlo, p_wohi, p_wolo, b_out, p_y);
    // 5) LayerNorm -> out
    ln_kernel<<<NN, 256>>>(gamma, beta, out);
}

// round 16
// speedup vs baseline: 1.4984x; 1.4984x over previous
#include <cuda_runtime.h>
#include <cuda_bf16.h>
#include <cuda_fp16.h>
#include <math.h>

#define NN  4096
#define EMB 256
#define NH  4
#define HC  64

typedef unsigned long long ull;

// ---- device scratch (no allocations allowed) ----
__device__ float    g_h[NN*EMB];
__device__ float    g_y[NN*EMB];
__device__ float    g_r[NH*NN];                 // e^{0.8 s_i}
__device__ float    g_ab[NH*NN*2];              // interleaved (e^{t_j}, e^{0.2 t_j})
__device__ unsigned g_adjbits[NN*(NN/32)];      // adjacency bitmask, diag=1
__device__ __half   g_hT[(size_t)NH*HC*NN];     // h transposed, fp16 (rn)
__device__ __nv_bfloat16 g_xhi[NN*EMB],  g_xlo[NN*EMB];    // x split (row-major)
__device__ __nv_bfloat16 g_atthi[NN*EMB], g_attlo[NN*EMB]; // att split (row-major)
__device__ __nv_bfloat16 g_wlhi[EMB*EMB], g_wllo[EMB*EMB]; // W_lin^T split [n][k]
__device__ __nv_bfloat16 g_wohi[EMB*EMB], g_wolo[EMB*EMB]; // W_out^T split [n][k]

__device__ __forceinline__ unsigned swz(unsigned o) { return o ^ ((o >> 3) & 0x70); }

__device__ __forceinline__ void ldsm4(unsigned& r0, unsigned& r1, unsigned& r2, unsigned& r3,
                                      unsigned a) {
    asm volatile("ldmatrix.sync.aligned.m8n8.x4.shared.b16 {%0,%1,%2,%3}, [%4];"
        : "=r"(r0), "=r"(r1), "=r"(r2), "=r"(r3) : "r"(a));
}
__device__ __forceinline__ void mma_bf(float* d, unsigned a0, unsigned a1, unsigned a2,
                                       unsigned a3, unsigned b0, unsigned b1) {
    asm volatile("mma.sync.aligned.m16n8k16.row.col.f32.bf16.bf16.f32 "
        "{%0,%1,%2,%3}, {%4,%5,%6,%7}, {%8,%9}, {%0,%1,%2,%3};"
        : "+f"(d[0]), "+f"(d[1]), "+f"(d[2]), "+f"(d[3])
        : "r"(a0), "r"(a1), "r"(a2), "r"(a3), "r"(b0), "r"(b1));
}
__device__ __forceinline__ void mma_h(float* d, unsigned a0, unsigned a1, unsigned a2,
                                      unsigned a3, unsigned b0, unsigned b1) {
    asm volatile("mma.sync.aligned.m16n8k16.row.col.f32.f16.f16.f32 "
        "{%0,%1,%2,%3}, {%4,%5,%6,%7}, {%8,%9}, {%0,%1,%2,%3};"
        : "+f"(d[0]), "+f"(d[1]), "+f"(d[2]), "+f"(d[3])
        : "r"(a0), "r"(a1), "r"(a2), "r"(a3), "r"(b0), "r"(b1));
}
__device__ __forceinline__ void cpa16(unsigned dst, const void* src) {
    asm volatile("cp.async.cg.shared.global [%0], [%1], 16;" :: "r"(dst), "l"(src));
}
__device__ __forceinline__ unsigned bfpairhi(float f0, float f1) {
    return __byte_perm(__float_as_uint(f0), __float_as_uint(f1), 0x7632);
}
__device__ __forceinline__ unsigned bfpairlo(float f0, float f1) {
    float r0 = f0 - __uint_as_float(__float_as_uint(f0) & 0xffff0000u);
    float r1 = f1 - __uint_as_float(__float_as_uint(f1) & 0xffff0000u);
    unsigned r; asm("cvt.rn.bf16x2.f32 %0, %1, %2;" : "=r"(r) : "f"(r1), "f"(r0));
    return r;
}

// ---------------------------------------------------------------------------
// Fused splits + adjbits (all HBM-bound, zero smem, merged into one launch):
//   blocks [0,2048)        : x -> bf16 hi/lo
//   blocks [2048,2176)     : W_lin split+transpose
//   blocks [2176,2304)     : W_out split+transpose
//   blocks [2304,2304+NN)  : adj row -> bitmask (forced self-loop)
// ---------------------------------------------------------------------------
__global__ __launch_bounds__(256) void split_adj_kernel(
    const float* __restrict__ x, const float* __restrict__ W_lin,
    const float* __restrict__ W_out, const int* __restrict__ adj)
{
    int b = blockIdx.x;
    if (b < 2048) {
        int i = b * 256 + threadIdx.x;
        float2 v = ((const float2*)x)[i];
        ((unsigned*)g_xhi)[i] = bfpairhi(v.x, v.y);
        ((unsigned*)g_xlo)[i] = bfpairlo(v.x, v.y);
    } else if (b < 2304) {
        const float* W = (b < 2176) ? W_lin : W_out;
        __nv_bfloat16* whi = (b < 2176) ? g_wlhi : g_wohi;
        __nv_bfloat16* wlo = (b < 2176) ? g_wllo : g_wolo;
        int idx = ((b - 2048) & 127) * 256 + threadIdx.x;
        int n = idx >> 7, kp = (idx & 127) * 2;
        float f0 = W[kp * EMB + n], f1 = W[(kp + 1) * EMB + n];
        ((unsigned*)whi)[n * 128 + (kp >> 1)] = bfpairhi(f0, f1);
        ((unsigned*)wlo)[n * 128 + (kp >> 1)] = bfpairlo(f0, f1);
    } else {
        int row  = b - 2304;
        int lane = threadIdx.x & 31;
        int w    = threadIdx.x >> 5;
#pragma unroll
        for (int wd = w; wd < NN/32; wd += 8) {
            int v = adj[(long)row * NN + wd * 32 + lane];
            unsigned bits = __ballot_sync(0xffffffffu, v != 0);
            if ((row >> 5) == wd) bits |= 1u << (row & 31);
            if (lane == 0) g_adjbits[row * (NN/32) + wd] = bits;
        }
    }
}

// ---------------------------------------------------------------------------
// Dense GEMM (R12 version): bf16 3-product, 2-stage cp.async, 256 threads,
// warp w: rows (w>>1)*32..+32, cols (w&1)*32..+32.
// ---------------------------------------------------------------------------
#define GM_A 0        // 2 bufs x (hi 16K + lo 16K)
#define GM_B 65536    // 2 bufs x (hi 8K + lo 8K)
#define GM_TOT 98304

__global__ __launch_bounds__(256) void gemm_mma_kernel(
    const __nv_bfloat16* __restrict__ Ahi, const __nv_bfloat16* __restrict__ Alo,
    const __nv_bfloat16* __restrict__ Bhi, const __nv_bfloat16* __restrict__ Blo,
    const float* __restrict__ bias, float* __restrict__ Co)
{
    extern __shared__ char smc[];
    const unsigned sb = (unsigned)__cvta_generic_to_shared(smc);
    const int tid  = threadIdx.x;
    const int m0   = blockIdx.y * 128;
    const int n0   = blockIdx.x * 64;
    const int lane = tid & 31;
    const int warp = tid >> 5;
    const int mrow  = (warp >> 1) * 32;
    const int nside = warp & 1;
    const int grp  = lane >> 3, lr = lane & 7;
    const unsigned afrag = (unsigned)(lr + ((grp & 1) << 3));
    const unsigned khalf = (unsigned)((grp >> 1) << 4);

    float acc[2][4][4];
#pragma unroll
    for (int m = 0; m < 2; m++)
#pragma unroll
        for (int n = 0; n < 4; n++)
#pragma unroll
            for (int e = 0; e < 4; e++) acc[m][n][e] = 0.f;

    auto load_chunk = [&](int kc, int buf) {
        const unsigned ab = GM_A + buf * 32768;
        const unsigned bb = GM_B + buf * 16384;
        const int k0 = kc * 64;
#pragma unroll
        for (int r = 0; r < 4; r++) {
            int ch = tid + r * 256;
            int row = ch >> 3, q = ch & 7;
            unsigned so = swz((unsigned)(row * 128 + q * 16));
            size_t off = (size_t)(m0 + row) * EMB + k0 + q * 8;
            cpa16(sb + ab + so,         Ahi + off);
            cpa16(sb + ab + 16384 + so, Alo + off);
        }
#pragma unroll
        for (int r = 0; r < 2; r++) {
            int ch = tid + r * 256;
            int n = ch >> 3, q = ch & 7;
            unsigned so = swz((unsigned)(n * 128 + q * 16));
            size_t off = (size_t)(n0 + n) * EMB + k0 + q * 8;
            cpa16(sb + bb + so,        Bhi + off);
            cpa16(sb + bb + 8192 + so, Blo + off);
        }
        asm volatile("cp.async.commit_group;" ::: "memory");
    };

    load_chunk(0, 0);
    for (int kc = 0; kc < 4; kc++) {
        const int buf = kc & 1;
        __syncthreads();
        if (kc < 3) load_chunk(kc + 1, buf ^ 1);
        if (kc < 3) { asm volatile("cp.async.wait_group 1;" ::: "memory"); }
        else        { asm volatile("cp.async.wait_group 0;" ::: "memory"); }
        __syncthreads();

        const unsigned ab = GM_A + buf * 32768;
        const unsigned bb = GM_B + buf * 16384;
#pragma unroll
        for (int kk = 0; kk < 4; kk++) {
            unsigned ah[2][4], al[2][4];
#pragma unroll
            for (int m = 0; m < 2; m++) {
                unsigned aoff = swz((unsigned)(mrow + m * 16 + afrag) * 128
                                    + (unsigned)(kk * 32) + khalf);
                ldsm4(ah[m][0], ah[m][1], ah[m][2], ah[m][3], sb + ab + aoff);
                ldsm4(al[m][0], al[m][1], al[m][2], al[m][3], sb + ab + 16384 + aoff);
            }
#pragma unroll
            for (int l = 0; l < 2; l++) {
                unsigned nrow = (unsigned)(nside * 32 + l * 16 + afrag);
                unsigned boff = swz(nrow * 128 + (unsigned)(kk * 32) + khalf);
                unsigned bh0, bh1, bh2, bh3, bl0, bl1, bl2, bl3;
                ldsm4(bh0, bh1, bh2, bh3, sb + bb + boff);
                ldsm4(bl0, bl1, bl2, bl3, sb + bb + 8192 + boff);
#pragma unroll
                for (int m = 0; m < 2; m++) {
                    mma_bf(acc[m][2*l],   ah[m][0], ah[m][1], ah[m][2], ah[m][3], bh0, bh2);
                    mma_bf(acc[m][2*l],   ah[m][0], ah[m][1], ah[m][2], ah[m][3], bl0, bl2);
                    mma_bf(acc[m][2*l],   al[m][0], al[m][1], al[m][2], al[m][3], bh0, bh2);
                    mma_bf(acc[m][2*l+1], ah[m][0], ah[m][1], ah[m][2], ah[m][3], bh1, bh3);
                    mma_bf(acc[m][2*l+1], ah[m][0], ah[m][1], ah[m][2], ah[m][3], bl1, bl3);
                    mma_bf(acc[m][2*l+1], al[m][0], al[m][1], al[m][2], al[m][3], bh1, bh3);
                }
            }
        }
    }

    int cb = (lane & 3) * 2;
#pragma unroll
    for (int m = 0; m < 2; m++) {
        int r0 = m0 + mrow + m * 16 + (lane >> 2);
        int r1 = r0 + 8;
#pragma unroll
        for (int j = 0; j < 4; j++) {
            int col = n0 + nside * 32 + j * 8 + cb;
            float b0 = bias ? __ldg(bias + col)     : 0.f;
            float b1 = bias ? __ldg(bias + col + 1) : 0.f;
            *(float2*)&Co[(size_t)r0 * EMB + col] =
                make_float2(acc[m][j][0] + b0, acc[m][j][1] + b1);
            *(float2*)&Co[(size_t)r1 * EMB + col] =
                make_float2(acc[m][j][2] + b0, acc[m][j][3] + b1);
        }
    }
}

// ---------------------------------------------------------------------------
// Fused ht + prep: block (jtile, head). Loads h tile once; emits transposed
// fp16 hT AND the per-node attention scalars r/ab for these 64 nodes.
// ---------------------------------------------------------------------------
__global__ __launch_bounds__(256) void ht_prep_kernel(
    const float* __restrict__ att_src, const float* __restrict__ att_dst)
{
    __shared__ float s[64][65];
    const int hd = blockIdx.y, jt = blockIdx.x * 64;
    const int t = threadIdx.x;
    {
        int r = t >> 2, cq = t & 3;
        const float4* src = (const float4*)(g_h + (size_t)(jt + r) * EMB + hd * HC + cq * 16);
#pragma unroll
        for (int u = 0; u < 4; u++) {
            float4 v = src[u];
            int cb = cq * 16 + u * 4;
            s[r][cb] = v.x; s[r][cb+1] = v.y; s[r][cb+2] = v.z; s[r][cb+3] = v.w;
        }
    }
    __syncthreads();

    // transpose -> fp16 hT
    {
        int c = t >> 2, jq = t & 3;
        unsigned hi[8];
#pragma unroll
        for (int e = 0; e < 8; e++) {
            __half2 hp = __floats2half2_rn(s[jq*16 + 2*e][c], s[jq*16 + 2*e + 1][c]);
            hi[e] = *(unsigned*)&hp;
        }
        size_t o = (size_t)(hd * HC + c) * NN + jt + jq * 16;
        *(uint4*)(g_hT + o)       = make_uint4(hi[0], hi[1], hi[2], hi[3]);
        *((uint4*)(g_hT + o) + 1) = make_uint4(hi[4], hi[5], hi[6], hi[7]);
    }

    // prep: 4 threads per node, 16 cols each
    {
        int node = t >> 2, q = t & 3;
        float sdot = 0.f, tdot = 0.f;
#pragma unroll
        for (int k = 0; k < 16; k++) {
            float hv = s[node][q * 16 + k];
            sdot += hv * __ldg(att_dst + hd * HC + q * 16 + k);
            tdot += hv * __ldg(att_src + hd * HC + q * 16 + k);
        }
        sdot += __shfl_xor_sync(0xffffffffu, sdot, 1);
        tdot += __shfl_xor_sync(0xffffffffu, tdot, 1);
        sdot += __shfl_xor_sync(0xffffffffu, sdot, 2);
        tdot += __shfl_xor_sync(0xffffffffu, tdot, 2);
        if (q == 0) {
            int idx = hd * NN + jt + node;
            g_r[idx]        = expf(0.8f * sdot);
            g_ab[2*idx]     = expf(tdot);
            g_ab[2*idx + 1] = expf(0.2f * tdot);
        }
    }
}

// ---------------------------------------------------------------------------
// GAT aggregation via mma.sync fp16, single product. 256 threads, 8 warps.
// Warp w: rows (w>>1)*32..+32, cols (w&1)*32..+32. Phase C: 2 thr/row, 32 j.
// Weights pre-scaled 1/16 (cancels in softmax). Double-buffered, 1 bar/tile.
// (Exact R12 configuration — verified local optimum.)
// ---------------------------------------------------------------------------
#define SM_AB   0         // 32768 B
#define SM_A    32768     // 2 bufs x 16384 (fp16 c)
#define SM_B    65536     // 2 bufs x 8192 (fp16 hT)
#define SM_D    81920     // 1024 B
#define SM_TOT  82944

__global__ __launch_bounds__(256) void gat_mma_kernel(const float* __restrict__ bias_att)
{
    extern __shared__ char smc[];
    const unsigned sb = (unsigned)__cvta_generic_to_shared(smc);
    const int tid  = threadIdx.x;
    const int hd   = blockIdx.y;
    const int i0   = blockIdx.x * 128;
    const int lane = tid & 31;
    const int warp = tid >> 5;
    const int mrow  = (warp >> 1) * 32;
    const int nside = warp & 1;

    {
        const float4* src = (const float4*)(g_ab + (size_t)hd * NN * 2);
        float4* dst = (float4*)(smc + SM_AB);
        for (int k = tid; k < NN / 2; k += 256) dst[k] = src[k];
    }

    const int row  = tid >> 1;
    const int half = tid & 1;
    const float ri = g_r[hd * NN + i0 + row] * 0.0625f;
    const unsigned* abw = g_adjbits + (size_t)(i0 + row) * (NN / 32);
    const float4* abt4  = (const float4*)(smc + SM_AB);
    float dreg = 0.f;

    const int grp = lane >> 3, lr = lane & 7;
    const unsigned khalf = (unsigned)((grp >> 1) << 4);
    const unsigned afrag = (unsigned)(lr + ((grp & 1) << 3));

    const __half* bsrc0 = g_hT + (size_t)hd * HC * NN;

    float acc[2][4][4];
#pragma unroll
    for (int m = 0; m < 2; m++)
#pragma unroll
        for (int n = 0; n < 4; n++)
#pragma unroll
            for (int e = 0; e < 4; e++) acc[m][n][e] = 0.f;

    __syncthreads();   // ab ready

    for (int t = 0; t < 64; t++) {
        const int j0  = t * 64;
        const int buf = t & 1;
        const unsigned abase = SM_A + buf * 16384;
        const unsigned bbase = SM_B + buf * 8192;

#pragma unroll
        for (int r = 0; r < 2; r++) {
            int ch = tid + r * 256;
            int cc = ch >> 3, q = ch & 7;
            unsigned so = swz((unsigned)(cc * 128 + q * 16));
            cpa16(sb + bbase + so, bsrc0 + (size_t)cc * NN + j0 + q * 8);
        }
        asm volatile("cp.async.commit_group;" ::: "memory");

        {
            unsigned wb = abw[(j0 >> 5) + half];
            const float4* abt = abt4 + (j0 >> 1) + half * 16;
#pragma unroll
            for (int q = 0; q < 4; q++) {
                unsigned hp4[4];
#pragma unroll
                for (int p = 0; p < 4; p++) {
                    float4 v = abt[q * 4 + p];
                    int sh = q * 8 + p * 2;
                    float c0 = ((wb >> sh) & 1u)       ? fmaxf(ri * v.x, 0.0625f * v.y) : 0.f;
                    float c1 = ((wb >> (sh + 1)) & 1u) ? fmaxf(ri * v.z, 0.0625f * v.w) : 0.f;
                    dreg += c0 + c1;
                    __half2 hh = __floats2half2_rn(c0, c1);
                    hp4[p] = *(unsigned*)&hh;
                }
                unsigned so = swz((unsigned)(row * 128 + half * 64 + q * 16));
                *(uint4*)(smc + abase + so) = make_uint4(hp4[0], hp4[1], hp4[2], hp4[3]);
            }
        }
        asm volatile("cp.async.wait_group 0;" ::: "memory");
        __syncthreads();

#pragma unroll
        for (int kk = 0; kk < 4; kk++) {
            unsigned a[2][4];
#pragma unroll
            for (int m = 0; m < 2; m++) {
                unsigned aoff = swz((unsigned)(mrow + m * 16 + afrag) * 128
                                    + (unsigned)(kk * 32) + khalf);
                ldsm4(a[m][0], a[m][1], a[m][2], a[m][3], sb + abase + aoff);
            }
#pragma unroll
            for (int l = 0; l < 2; l++) {
                unsigned nrow = (unsigned)(nside * 32 + l * 16 + afrag);
                unsigned boff = swz(nrow * 128 + (unsigned)(kk * 32) + khalf);
                unsigned b0, b1, b2, b3;
                ldsm4(b0, b1, b2, b3, sb + bbase + boff);
#pragma unroll
                for (int m = 0; m < 2; m++) {
                    mma_h(acc[m][2*l],   a[m][0], a[m][1], a[m][2], a[m][3], b0, b2);
                    mma_h(acc[m][2*l+1], a[m][0], a[m][1], a[m][2], a[m][3], b1, b3);
                }
            }
        }
    }

    ((float*)(smc + SM_D))[tid] = dreg;
    __syncthreads();

    {
        const float* dsm = (const float*)(smc + SM_D);
        int cb = (lane & 3) * 2;
#pragma unroll
        for (int m = 0; m < 2; m++) {
            int r0 = mrow + m * 16 + (lane >> 2);
            int r1 = r0 + 8;
            float inv0 = 1.0f / (dsm[2*r0] + dsm[2*r0 + 1]);
            float inv1 = 1.0f / (dsm[2*r1] + dsm[2*r1 + 1]);
#pragma unroll
            for (int j = 0; j < 4; j++) {
                int col = nside * 32 + j * 8 + cb;
                float b0 = __ldg(bias_att + hd * HC + col);
                float b1 = __ldg(bias_att + hd * HC + col + 1);
                float v00 = acc[m][j][0] * inv0 + b0, v01 = acc[m][j][1] * inv0 + b1;
                float v10 = acc[m][j][2] * inv1 + b0, v11 = acc[m][j][3] * inv1 + b1;
                size_t o0 = ((size_t)(i0 + r0) * EMB + hd * HC + col) >> 1;
                size_t o1 = ((size_t)(i0 + r1) * EMB + hd * HC + col) >> 1;
                ((unsigned*)g_atthi)[o0] = bfpairhi(v00, v01);
                ((unsigned*)g_attlo)[o0] = bfpairlo(v00, v01);
                ((unsigned*)g_atthi)[o1] = bfpairhi(v10, v11);
                ((unsigned*)g_attlo)[o1] = bfpairlo(v10, v11);
            }
        }
    }
}

// ---------------------------------------------------------------------------
// LayerNorm over last dim (256), one block per row.
// ---------------------------------------------------------------------------
__global__ __launch_bounds__(256) void ln_kernel(
    const float* __restrict__ gamma, const float* __restrict__ beta,
    float* __restrict__ out)
{
    __shared__ float red1[8], red2[8];
    int row = blockIdx.x;
    int tid = threadIdx.x;
    float v = g_y[row * EMB + tid];

    float s = v;
#pragma unroll
    for (int o = 16; o; o >>= 1) s += __shfl_xor_sync(0xffffffffu, s, o);
    if ((tid & 31) == 0) red1[tid >> 5] = s;
    __syncthreads();
    float mu = 0.f;
#pragma unroll
    for (int k = 0; k < 8; k++) mu += red1[k];
    mu *= (1.0f / EMB);

    float d = v - mu;
    float q = d * d;
#pragma unroll
    for (int o = 16; o; o >>= 1) q += __shfl_xor_sync(0xffffffffu, q, o);
    if ((tid & 31) == 0) red2[tid >> 5] = q;
    __syncthreads();
    float var = 0.f;
#pragma unroll
    for (int k = 0; k < 8; k++) var += red2[k];
    var *= (1.0f / EMB);

    out[row * EMB + tid] = d * rsqrtf(var + 1e-5f) * gamma[tid] + beta[tid];
}

// ---------------------------------------------------------------------------
extern "C" void kernel_launch(void* const* d_in, const int* in_sizes, int n_in,
                              void* d_out, int out_size)
{
    const float* x        = (const float*)d_in[0];
    const int*   adj      = (const int*)  d_in[1];
    const float* W_lin    = (const float*)d_in[2];
    const float* att_src  = (const float*)d_in[3];
    const float* att_dst  = (const float*)d_in[4];
    const float* bias_att = (const float*)d_in[5];
    const float* W_out    = (const float*)d_in[6];
    const float* b_out    = (const float*)d_in[7];
    const float* gamma    = (const float*)d_in[8];
    const float* beta     = (const float*)d_in[9];
    float* out = (float*)d_out;

    float *p_h, *p_y;
    cudaGetSymbolAddress((void**)&p_h, g_h);
    cudaGetSymbolAddress((void**)&p_y, g_y);
    __nv_bfloat16 *p_xhi, *p_xlo, *p_athi, *p_atlo, *p_wlhi, *p_wllo, *p_wohi, *p_wolo;
    cudaGetSymbolAddress((void**)&p_xhi,  g_xhi);
    cudaGetSymbolAddress((void**)&p_xlo,  g_xlo);
    cudaGetSymbolAddress((void**)&p_athi, g_atthi);
    cudaGetSymbolAddress((void**)&p_atlo, g_attlo);
    cudaGetSymbolAddress((void**)&p_wlhi, g_wlhi);
    cudaGetSymbolAddress((void**)&p_wllo, g_wllo);
    cudaGetSymbolAddress((void**)&p_wohi, g_wohi);
    cudaGetSymbolAddress((void**)&p_wolo, g_wolo);

    cudaFuncSetAttribute(gat_mma_kernel,  cudaFuncAttributeMaxDynamicSharedMemorySize, SM_TOT);
    cudaFuncSetAttribute(gemm_mma_kernel, cudaFuncAttributeMaxDynamicSharedMemorySize, GM_TOT);

    dim3 gemm_grid(EMB / 64, NN / 128);  // (4, 32) = 128 blocks

    // splits + adjbits (all independent HBM work, one launch)
    split_adj_kernel<<<2304 + NN, 256>>>(x, W_lin, W_out, adj);
    // 1) h = x @ W_lin
    gemm_mma_kernel<<<gemm_grid, 256, GM_TOT>>>(p_xhi, p_xlo, p_wlhi, p_wllo, nullptr, p_h);
    // 2) fused transpose + attention scalars
    ht_prep_kernel<<<dim3(NN / 64, NH), 256>>>(att_src, att_dst);
    // 3) fp16 single-product masked-softmax aggregation (+bias_att) -> att hi/lo
    gat_mma_kernel<<<dim3(NN / 128, NH), 256, SM_TOT>>>(bias_att);
    // 4) y = att @ W_out + b_out
    gemm_mma_kernel<<<gemm_grid, 256, GM_TOT>>>(p_athi, p_atlo, p_wohi, p_wolo, b_out, p_y);
    // 5) LayerNorm -> out
    ln_kernel<<<NN, 256>>>(gamma, beta, out);
}

// round 17
// speedup vs baseline: 1.5347x; 1.0242x over previous
#include <cuda_runtime.h>
#include <cuda_bf16.h>
#include <cuda_fp16.h>
#include <math.h>

#define NN  4096
#define EMB 256
#define NH  4
#define HC  64

typedef unsigned long long ull;

// ---- device scratch (no allocations allowed) ----
__device__ float    g_h[NN*EMB];
__device__ float    g_y[NN*EMB];
__device__ float    g_r[NH*NN];                 // e^{0.8 s_i}
__device__ float    g_ab[NH*NN*2];              // interleaved (e^{t_j}, e^{0.2 t_j})
__device__ unsigned g_adjbits[NN*(NN/32)];      // adjacency bitmask, diag=1
__device__ __half   g_hT[(size_t)NH*HC*NN];     // h transposed, fp16 (rn)
__device__ float    g_part[2][NN*EMB];          // split-K partial aggregates
__device__ float    g_dpart[2][NH*NN];          // split-K partial denominators
__device__ __nv_bfloat16 g_xhi[NN*EMB],  g_xlo[NN*EMB];    // x split (row-major)
__device__ __nv_bfloat16 g_atthi[NN*EMB], g_attlo[NN*EMB]; // att split (row-major)
__device__ __nv_bfloat16 g_wlhi[EMB*EMB], g_wllo[EMB*EMB]; // W_lin^T split [n][k]
__device__ __nv_bfloat16 g_wohi[EMB*EMB], g_wolo[EMB*EMB]; // W_out^T split [n][k]

__device__ __forceinline__ unsigned swz(unsigned o) { return o ^ ((o >> 3) & 0x70); }

__device__ __forceinline__ void ldsm4(unsigned& r0, unsigned& r1, unsigned& r2, unsigned& r3,
                                      unsigned a) {
    asm volatile("ldmatrix.sync.aligned.m8n8.x4.shared.b16 {%0,%1,%2,%3}, [%4];"
        : "=r"(r0), "=r"(r1), "=r"(r2), "=r"(r3) : "r"(a));
}
__device__ __forceinline__ void mma_bf(float* d, unsigned a0, unsigned a1, unsigned a2,
                                       unsigned a3, unsigned b0, unsigned b1) {
    asm volatile("mma.sync.aligned.m16n8k16.row.col.f32.bf16.bf16.f32 "
        "{%0,%1,%2,%3}, {%4,%5,%6,%7}, {%8,%9}, {%0,%1,%2,%3};"
        : "+f"(d[0]), "+f"(d[1]), "+f"(d[2]), "+f"(d[3])
        : "r"(a0), "r"(a1), "r"(a2), "r"(a3), "r"(b0), "r"(b1));
}
__device__ __forceinline__ void mma_h(float* d, unsigned a0, unsigned a1, unsigned a2,
                                      unsigned a3, unsigned b0, unsigned b1) {
    asm volatile("mma.sync.aligned.m16n8k16.row.col.f32.f16.f16.f32 "
        "{%0,%1,%2,%3}, {%4,%5,%6,%7}, {%8,%9}, {%0,%1,%2,%3};"
        : "+f"(d[0]), "+f"(d[1]), "+f"(d[2]), "+f"(d[3])
        : "r"(a0), "r"(a1), "r"(a2), "r"(a3), "r"(b0), "r"(b1));
}
__device__ __forceinline__ void cpa16(unsigned dst, const void* src) {
    asm volatile("cp.async.cg.shared.global [%0], [%1], 16;" :: "r"(dst), "l"(src));
}
__device__ __forceinline__ unsigned bfpairhi(float f0, float f1) {
    return __byte_perm(__float_as_uint(f0), __float_as_uint(f1), 0x7632);
}
__device__ __forceinline__ unsigned bfpairlo(float f0, float f1) {
    float r0 = f0 - __uint_as_float(__float_as_uint(f0) & 0xffff0000u);
    float r1 = f1 - __uint_as_float(__float_as_uint(f1) & 0xffff0000u);
    unsigned r; asm("cvt.rn.bf16x2.f32 %0, %1, %2;" : "=r"(r) : "f"(r1), "f"(r0));
    return r;
}

// ---------------------------------------------------------------------------
// Fused splits + adjbits (all HBM-bound, zero smem).
// ---------------------------------------------------------------------------
__global__ __launch_bounds__(256) void split_adj_kernel(
    const float* __restrict__ x, const float* __restrict__ W_lin,
    const float* __restrict__ W_out, const int* __restrict__ adj)
{
    int b = blockIdx.x;
    if (b < 2048) {
        int i = b * 256 + threadIdx.x;
        float2 v = ((const float2*)x)[i];
        ((unsigned*)g_xhi)[i] = bfpairhi(v.x, v.y);
        ((unsigned*)g_xlo)[i] = bfpairlo(v.x, v.y);
    } else if (b < 2304) {
        const float* W = (b < 2176) ? W_lin : W_out;
        __nv_bfloat16* whi = (b < 2176) ? g_wlhi : g_wohi;
        __nv_bfloat16* wlo = (b < 2176) ? g_wllo : g_wolo;
        int idx = ((b - 2048) & 127) * 256 + threadIdx.x;
        int n = idx >> 7, kp = (idx & 127) * 2;
        float f0 = W[kp * EMB + n], f1 = W[(kp + 1) * EMB + n];
        ((unsigned*)whi)[n * 128 + (kp >> 1)] = bfpairhi(f0, f1);
        ((unsigned*)wlo)[n * 128 + (kp >> 1)] = bfpairlo(f0, f1);
    } else {
        int row  = b - 2304;
        int lane = threadIdx.x & 31;
        int w    = threadIdx.x >> 5;
#pragma unroll
        for (int wd = w; wd < NN/32; wd += 8) {
            int v = adj[(long)row * NN + wd * 32 + lane];
            unsigned bits = __ballot_sync(0xffffffffu, v != 0);
            if ((row >> 5) == wd) bits |= 1u << (row & 31);
            if (lane == 0) g_adjbits[row * (NN/32) + wd] = bits;
        }
    }
}

// ---------------------------------------------------------------------------
// Dense GEMM (R12): bf16 3-product, 2-stage cp.async, 256 threads.
// ---------------------------------------------------------------------------
#define GM_A 0
#define GM_B 65536
#define GM_TOT 98304

__global__ __launch_bounds__(256) void gemm_mma_kernel(
    const __nv_bfloat16* __restrict__ Ahi, const __nv_bfloat16* __restrict__ Alo,
    const __nv_bfloat16* __restrict__ Bhi, const __nv_bfloat16* __restrict__ Blo,
    const float* __restrict__ bias, float* __restrict__ Co)
{
    extern __shared__ char smc[];
    const unsigned sb = (unsigned)__cvta_generic_to_shared(smc);
    const int tid  = threadIdx.x;
    const int m0   = blockIdx.y * 128;
    const int n0   = blockIdx.x * 64;
    const int lane = tid & 31;
    const int warp = tid >> 5;
    const int mrow  = (warp >> 1) * 32;
    const int nside = warp & 1;
    const int grp  = lane >> 3, lr = lane & 7;
    const unsigned afrag = (unsigned)(lr + ((grp & 1) << 3));
    const unsigned khalf = (unsigned)((grp >> 1) << 4);

    float acc[2][4][4];
#pragma unroll
    for (int m = 0; m < 2; m++)
#pragma unroll
        for (int n = 0; n < 4; n++)
#pragma unroll
            for (int e = 0; e < 4; e++) acc[m][n][e] = 0.f;

    auto load_chunk = [&](int kc, int buf) {
        const unsigned ab = GM_A + buf * 32768;
        const unsigned bb = GM_B + buf * 16384;
        const int k0 = kc * 64;
#pragma unroll
        for (int r = 0; r < 4; r++) {
            int ch = tid + r * 256;
            int row = ch >> 3, q = ch & 7;
            unsigned so = swz((unsigned)(row * 128 + q * 16));
            size_t off = (size_t)(m0 + row) * EMB + k0 + q * 8;
            cpa16(sb + ab + so,         Ahi + off);
            cpa16(sb + ab + 16384 + so, Alo + off);
        }
#pragma unroll
        for (int r = 0; r < 2; r++) {
            int ch = tid + r * 256;
            int n = ch >> 3, q = ch & 7;
            unsigned so = swz((unsigned)(n * 128 + q * 16));
            size_t off = (size_t)(n0 + n) * EMB + k0 + q * 8;
            cpa16(sb + bb + so,        Bhi + off);
            cpa16(sb + bb + 8192 + so, Blo + off);
        }
        asm volatile("cp.async.commit_group;" ::: "memory");
    };

    load_chunk(0, 0);
    for (int kc = 0; kc < 4; kc++) {
        const int buf = kc & 1;
        __syncthreads();
        if (kc < 3) load_chunk(kc + 1, buf ^ 1);
        if (kc < 3) { asm volatile("cp.async.wait_group 1;" ::: "memory"); }
        else        { asm volatile("cp.async.wait_group 0;" ::: "memory"); }
        __syncthreads();

        const unsigned ab = GM_A + buf * 32768;
        const unsigned bb = GM_B + buf * 16384;
#pragma unroll
        for (int kk = 0; kk < 4; kk++) {
            unsigned ah[2][4], al[2][4];
#pragma unroll
            for (int m = 0; m < 2; m++) {
                unsigned aoff = swz((unsigned)(mrow + m * 16 + afrag) * 128
                                    + (unsigned)(kk * 32) + khalf);
                ldsm4(ah[m][0], ah[m][1], ah[m][2], ah[m][3], sb + ab + aoff);
                ldsm4(al[m][0], al[m][1], al[m][2], al[m][3], sb + ab + 16384 + aoff);
            }
#pragma unroll
            for (int l = 0; l < 2; l++) {
                unsigned nrow = (unsigned)(nside * 32 + l * 16 + afrag);
                unsigned boff = swz(nrow * 128 + (unsigned)(kk * 32) + khalf);
                unsigned bh0, bh1, bh2, bh3, bl0, bl1, bl2, bl3;
                ldsm4(bh0, bh1, bh2, bh3, sb + bb + boff);
                ldsm4(bl0, bl1, bl2, bl3, sb + bb + 8192 + boff);
#pragma unroll
                for (int m = 0; m < 2; m++) {
                    mma_bf(acc[m][2*l],   ah[m][0], ah[m][1], ah[m][2], ah[m][3], bh0, bh2);
                    mma_bf(acc[m][2*l],   ah[m][0], ah[m][1], ah[m][2], ah[m][3], bl0, bl2);
                    mma_bf(acc[m][2*l],   al[m][0], al[m][1], al[m][2], al[m][3], bh0, bh2);
                    mma_bf(acc[m][2*l+1], ah[m][0], ah[m][1], ah[m][2], ah[m][3], bh1, bh3);
                    mma_bf(acc[m][2*l+1], ah[m][0], ah[m][1], ah[m][2], ah[m][3], bl1, bl3);
                    mma_bf(acc[m][2*l+1], al[m][0], al[m][1], al[m][2], al[m][3], bh1, bh3);
                }
            }
        }
    }

    int cb = (lane & 3) * 2;
#pragma unroll
    for (int m = 0; m < 2; m++) {
        int r0 = m0 + mrow + m * 16 + (lane >> 2);
        int r1 = r0 + 8;
#pragma unroll
        for (int j = 0; j < 4; j++) {
            int col = n0 + nside * 32 + j * 8 + cb;
            float b0 = bias ? __ldg(bias + col)     : 0.f;
            float b1 = bias ? __ldg(bias + col + 1) : 0.f;
            *(float2*)&Co[(size_t)r0 * EMB + col] =
                make_float2(acc[m][j][0] + b0, acc[m][j][1] + b1);
            *(float2*)&Co[(size_t)r1 * EMB + col] =
                make_float2(acc[m][j][2] + b0, acc[m][j][3] + b1);
        }
    }
}

// ---------------------------------------------------------------------------
// Fused ht + prep (unchanged).
// ---------------------------------------------------------------------------
__global__ __launch_bounds__(256) void ht_prep_kernel(
    const float* __restrict__ att_src, const float* __restrict__ att_dst)
{
    __shared__ float s[64][65];
    const int hd = blockIdx.y, jt = blockIdx.x * 64;
    const int t = threadIdx.x;
    {
        int r = t >> 2, cq = t & 3;
        const float4* src = (const float4*)(g_h + (size_t)(jt + r) * EMB + hd * HC + cq * 16);
#pragma unroll
        for (int u = 0; u < 4; u++) {
            float4 v = src[u];
            int cb = cq * 16 + u * 4;
            s[r][cb] = v.x; s[r][cb+1] = v.y; s[r][cb+2] = v.z; s[r][cb+3] = v.w;
        }
    }
    __syncthreads();
    {
        int c = t >> 2, jq = t & 3;
        unsigned hi[8];
#pragma unroll
        for (int e = 0; e < 8; e++) {
            __half2 hp = __floats2half2_rn(s[jq*16 + 2*e][c], s[jq*16 + 2*e + 1][c]);
            hi[e] = *(unsigned*)&hp;
        }
        size_t o = (size_t)(hd * HC + c) * NN + jt + jq * 16;
        *(uint4*)(g_hT + o)       = make_uint4(hi[0], hi[1], hi[2], hi[3]);
        *((uint4*)(g_hT + o) + 1) = make_uint4(hi[4], hi[5], hi[6], hi[7]);
    }
    {
        int node = t >> 2, q = t & 3;
        float sdot = 0.f, tdot = 0.f;
#pragma unroll
        for (int k = 0; k < 16; k++) {
            float hv = s[node][q * 16 + k];
            sdot += hv * __ldg(att_dst + hd * HC + q * 16 + k);
            tdot += hv * __ldg(att_src + hd * HC + q * 16 + k);
        }
        sdot += __shfl_xor_sync(0xffffffffu, sdot, 1);
        tdot += __shfl_xor_sync(0xffffffffu, tdot, 1);
        sdot += __shfl_xor_sync(0xffffffffu, sdot, 2);
        tdot += __shfl_xor_sync(0xffffffffu, tdot, 2);
        if (q == 0) {
            int idx = hd * NN + jt + node;
            g_r[idx]        = expf(0.8f * sdot);
            g_ab[2*idx]     = expf(tdot);
            g_ab[2*idx + 1] = expf(0.2f * tdot);
        }
    }
}

// ---------------------------------------------------------------------------
// Split-K GAT aggregation: grid (32, 4, 2). Block (i,hd,jh) does j in
// [jh*2048, +2048). smem 66.5KB -> 2 blocks/SM resident. Writes unnormalized
// partial D + partial denominators; att_reduce merges.
// ---------------------------------------------------------------------------
#define SM_AB   0         // 16384 B (half-head ab)
#define SM_A    16384     // 2 bufs x 16384 (fp16 c)
#define SM_B    49152     // 2 bufs x 8192 (fp16 hT)
#define SM_D    65536     // 1024 B
#define SM_TOT  66560

__global__ __launch_bounds__(256) void gat_mma_kernel()
{
    extern __shared__ char smc[];
    const unsigned sb = (unsigned)__cvta_generic_to_shared(smc);
    const int tid  = threadIdx.x;
    const int hd   = blockIdx.y;
    const int i0   = blockIdx.x * 128;
    const int jh   = blockIdx.z;          // 0/1: j half
    const int jg0  = jh * (NN / 2);       // global j base
    const int lane = tid & 31;
    const int warp = tid >> 5;
    const int mrow  = (warp >> 1) * 32;
    const int nside = warp & 1;

    // preload (a,b) pairs for THIS HALF of the head: 2048 pairs = 16KB
    {
        const float4* src = (const float4*)(g_ab + (size_t)hd * NN * 2 + jg0 * 2);
        float4* dst = (float4*)(smc + SM_AB);
        for (int k = tid; k < NN / 4; k += 256) dst[k] = src[k];
    }

    const int row  = tid >> 1;
    const int half = tid & 1;
    const float ri = g_r[hd * NN + i0 + row] * 0.0625f;
    const unsigned* abw = g_adjbits + (size_t)(i0 + row) * (NN / 32);
    const float4* abt4  = (const float4*)(smc + SM_AB);
    float dreg = 0.f;

    const int grp = lane >> 3, lr = lane & 7;
    const unsigned khalf = (unsigned)((grp >> 1) << 4);
    const unsigned afrag = (unsigned)(lr + ((grp & 1) << 3));

    const __half* bsrc0 = g_hT + (size_t)hd * HC * NN;

    float acc[2][4][4];
#pragma unroll
    for (int m = 0; m < 2; m++)
#pragma unroll
        for (int n = 0; n < 4; n++)
#pragma unroll
            for (int e = 0; e < 4; e++) acc[m][n][e] = 0.f;

    __syncthreads();   // ab ready

    for (int t = 0; t < 32; t++) {
        const int j0  = t * 64;            // local within half
        const int jg  = jg0 + j0;          // global
        const int buf = t & 1;
        const unsigned abase = SM_A + buf * 16384;
        const unsigned bbase = SM_B + buf * 8192;

#pragma unroll
        for (int r = 0; r < 2; r++) {
            int ch = tid + r * 256;
            int cc = ch >> 3, q = ch & 7;
            unsigned so = swz((unsigned)(cc * 128 + q * 16));
            cpa16(sb + bbase + so, bsrc0 + (size_t)cc * NN + jg + q * 8);
        }
        asm volatile("cp.async.commit_group;" ::: "memory");

        {
            unsigned wb = abw[(jg >> 5) + half];
            const float4* abt = abt4 + (j0 >> 1) + half * 16;
#pragma unroll
            for (int q = 0; q < 4; q++) {
                unsigned hp4[4];
#pragma unroll
                for (int p = 0; p < 4; p++) {
                    float4 v = abt[q * 4 + p];
                    int sh = q * 8 + p * 2;
                    float c0 = ((wb >> sh) & 1u)       ? fmaxf(ri * v.x, 0.0625f * v.y) : 0.f;
                    float c1 = ((wb >> (sh + 1)) & 1u) ? fmaxf(ri * v.z, 0.0625f * v.w) : 0.f;
                    dreg += c0 + c1;
                    __half2 hh = __floats2half2_rn(c0, c1);
                    hp4[p] = *(unsigned*)&hh;
                }
                unsigned so = swz((unsigned)(row * 128 + half * 64 + q * 16));
                *(uint4*)(smc + abase + so) = make_uint4(hp4[0], hp4[1], hp4[2], hp4[3]);
            }
        }
        asm volatile("cp.async.wait_group 0;" ::: "memory");
        __syncthreads();

#pragma unroll
        for (int kk = 0; kk < 4; kk++) {
            unsigned a[2][4];
#pragma unroll
            for (int m = 0; m < 2; m++) {
                unsigned aoff = swz((unsigned)(mrow + m * 16 + afrag) * 128
                                    + (unsigned)(kk * 32) + khalf);
                ldsm4(a[m][0], a[m][1], a[m][2], a[m][3], sb + abase + aoff);
            }
#pragma unroll
            for (int l = 0; l < 2; l++) {
                unsigned nrow = (unsigned)(nside * 32 + l * 16 + afrag);
                unsigned boff = swz(nrow * 128 + (unsigned)(kk * 32) + khalf);
                unsigned b0, b1, b2, b3;
                ldsm4(b0, b1, b2, b3, sb + bbase + boff);
#pragma unroll
                for (int m = 0; m < 2; m++) {
                    mma_h(acc[m][2*l],   a[m][0], a[m][1], a[m][2], a[m][3], b0, b2);
                    mma_h(acc[m][2*l+1], a[m][0], a[m][1], a[m][2], a[m][3], b1, b3);
                }
            }
        }
    }

    ((float*)(smc + SM_D))[tid] = dreg;
    __syncthreads();

    // write partial denominators + unnormalized partial D
    if (tid < 128) {
        const float* dsm = (const float*)(smc + SM_D);
        g_dpart[jh][hd * NN + i0 + tid] = dsm[2 * tid] + dsm[2 * tid + 1];
    }
    {
        float* gp = g_part[jh];
        int cb = (lane & 3) * 2;
#pragma unroll
        for (int m = 0; m < 2; m++) {
            int r0 = i0 + mrow + m * 16 + (lane >> 2);
            int r1 = r0 + 8;
#pragma unroll
            for (int j = 0; j < 4; j++) {
                int col = hd * HC + nside * 32 + j * 8 + cb;
                *(float2*)&gp[(size_t)r0 * EMB + col] =
                    make_float2(acc[m][j][0], acc[m][j][1]);
                *(float2*)&gp[(size_t)r1 * EMB + col] =
                    make_float2(acc[m][j][2], acc[m][j][3]);
            }
        }
    }
}

// ---------------------------------------------------------------------------
// Reduce split-K partials: att = (P0+P1)/(d0+d1) + bias -> bf16 hi/lo.
// Block = 2 rows x 128 float2-columns.
// ---------------------------------------------------------------------------
__global__ __launch_bounds__(256) void att_reduce_kernel(const float* __restrict__ bias_att)
{
    int row = blockIdx.x * 2 + (threadIdx.x >> 7);
    int cp  = threadIdx.x & 127;          // float2 index, cols cp*2, cp*2+1
    int col = cp * 2;
    int hd  = col >> 6;
    float2 p0 = ((const float2*)g_part[0])[(size_t)row * 128 + cp];
    float2 p1 = ((const float2*)g_part[1])[(size_t)row * 128 + cp];
    float inv = 1.0f / (g_dpart[0][hd * NN + row] + g_dpart[1][hd * NN + row]);
    float v0 = (p0.x + p1.x) * inv + __ldg(bias_att + col);
    float v1 = (p0.y + p1.y) * inv + __ldg(bias_att + col + 1);
    ((unsigned*)g_atthi)[(size_t)row * 128 + cp] = bfpairhi(v0, v1);
    ((unsigned*)g_attlo)[(size_t)row * 128 + cp] = bfpairlo(v0, v1);
}

// ---------------------------------------------------------------------------
// LayerNorm over last dim (256), one block per row.
// ---------------------------------------------------------------------------
__global__ __launch_bounds__(256) void ln_kernel(
    const float* __restrict__ gamma, const float* __restrict__ beta,
    float* __restrict__ out)
{
    __shared__ float red1[8], red2[8];
    int row = blockIdx.x;
    int tid = threadIdx.x;
    float v = g_y[row * EMB + tid];

    float s = v;
#pragma unroll
    for (int o = 16; o; o >>= 1) s += __shfl_xor_sync(0xffffffffu, s, o);
    if ((tid & 31) == 0) red1[tid >> 5] = s;
    __syncthreads();
    float mu = 0.f;
#pragma unroll
    for (int k = 0; k < 8; k++) mu += red1[k];
    mu *= (1.0f / EMB);

    float d = v - mu;
    float q = d * d;
#pragma unroll
    for (int o = 16; o; o >>= 1) q += __shfl_xor_sync(0xffffffffu, q, o);
    if ((tid & 31) == 0) red2[tid >> 5] = q;
    __syncthreads();
    float var = 0.f;
#pragma unroll
    for (int k = 0; k < 8; k++) var += red2[k];
    var *= (1.0f / EMB);

    out[row * EMB + tid] = d * rsqrtf(var + 1e-5f) * gamma[tid] + beta[tid];
}

// ---------------------------------------------------------------------------
extern "C" void kernel_launch(void* const* d_in, const int* in_sizes, int n_in,
                              void* d_out, int out_size)
{
    const float* x        = (const float*)d_in[0];
    const int*   adj      = (const int*)  d_in[1];
    const float* W_lin    = (const float*)d_in[2];
    const float* att_src  = (const float*)d_in[3];
    const float* att_dst  = (const float*)d_in[4];
    const float* bias_att = (const float*)d_in[5];
    const float* W_out    = (const float*)d_in[6];
    const float* b_out    = (const float*)d_in[7];
    const float* gamma    = (const float*)d_in[8];
    const float* beta     = (const float*)d_in[9];
    float* out = (float*)d_out;

    float *p_h, *p_y;
    cudaGetSymbolAddress((void**)&p_h, g_h);
    cudaGetSymbolAddress((void**)&p_y, g_y);
    __nv_bfloat16 *p_xhi, *p_xlo, *p_athi, *p_atlo, *p_wlhi, *p_wllo, *p_wohi, *p_wolo;
    cudaGetSymbolAddress((void**)&p_xhi,  g_xhi);
    cudaGetSymbolAddress((void**)&p_xlo,  g_xlo);
    cudaGetSymbolAddress((void**)&p_athi, g_atthi);
    cudaGetSymbolAddress((void**)&p_atlo, g_attlo);
    cudaGetSymbolAddress((void**)&p_wlhi, g_wlhi);
    cudaGetSymbolAddress((void**)&p_wllo, g_wllo);
    cudaGetSymbolAddress((void**)&p_wohi, g_wohi);
    cudaGetSymbolAddress((void**)&p_wolo, g_wolo);

    cudaFuncSetAttribute(gat_mma_kernel,  cudaFuncAttributeMaxDynamicSharedMemorySize, SM_TOT);
    cudaFuncSetAttribute(gemm_mma_kernel, cudaFuncAttributeMaxDynamicSharedMemorySize, GM_TOT);

    dim3 gemm_grid(EMB / 64, NN / 128);  // (4, 32) = 128 blocks

    // splits + adjbits (all independent HBM work, one launch)
    split_adj_kernel<<<2304 + NN, 256>>>(x, W_lin, W_out, adj);
    // 1) h = x @ W_lin
    gemm_mma_kernel<<<gemm_grid, 256, GM_TOT>>>(p_xhi, p_xlo, p_wlhi, p_wllo, nullptr, p_h);
    // 2) fused transpose + attention scalars
    ht_prep_kernel<<<dim3(NN / 64, NH), 256>>>(att_src, att_dst);
    // 3) split-K fp16 masked-softmax aggregation -> partials
    gat_mma_kernel<<<dim3(NN / 128, NH, 2), 256, SM_TOT>>>();
    // 3b) reduce partials, normalize, +bias, split bf16
    att_reduce_kernel<<<NN / 2, 256>>>(bias_att);
    // 4) y = att @ W_out + b_out
    gemm_mma_kernel<<<gemm_grid, 256, GM_TOT>>>(p_athi, p_atlo, p_wohi, p_wolo, b_out, p_y);
    // 5) LayerNorm -> out
    ln_kernel<<<NN, 256>>>(gamma, beta, out);
}